// round 2
// baseline (speedup 1.0000x reference)
#include <cuda_runtime.h>
#include <math.h>

// Problem constants
#define T_TOK   16384      // B*S = 4*4096
#define D_DIM   2048
#define E_EXP   64
#define TOK_TILE 128
#define DK      32         // D chunk per smem stage
#define NCHUNK  (D_DIM / DK)       // 64
#define NBLK    (T_TOK / TOK_TILE) // 128
#define XROW    36         // DK + 4 pad (multiple of 4 for float4)
#define PROW    65         // prob row pad

// Deterministic per-block usage partial sums (no atomics)
__device__ float g_partial[NBLK * E_EXP];

__global__ __launch_bounds__(256, 1)
void router_main(const float* __restrict__ x, const float* __restrict__ W,
                 float* __restrict__ out, int out_size)
{
    // smem union: mainloop tiles overlap with epilogue prob matrix
    __shared__ __align__(16) unsigned char smem_raw[33280 + 512];
    float (*xs)[XROW]  = reinterpret_cast<float(*)[XROW]>(smem_raw);            // [128][36] = 18432 B
    float (*ws)[XROW]  = reinterpret_cast<float(*)[XROW]>(smem_raw + 18432);    // [64][36]  =  9216 B
    float (*probs)[PROW] = reinterpret_cast<float(*)[PROW]>(smem_raw);          // [128][65] = 33280 B
    float* rZ = reinterpret_cast<float*>(smem_raw + 33280);                     // [128]

    const int tid = threadIdx.x;
    const int blk = blockIdx.x;
    const int tx  = tid & 15;   // expert group: experts tx + 16*j
    const int ty  = tid >> 4;   // token group: tokens ty*8 .. ty*8+7
    const int tok_base = blk * TOK_TILE;

    float acc[8][4];
#pragma unroll
    for (int i = 0; i < 8; i++)
#pragma unroll
        for (int j = 0; j < 4; j++) acc[i][j] = 0.0f;

    // prefetch registers
    float4 px[4], pw[2];

    // load assignment for x chunk: 1024 float4 (128 rows x 8), 4 per thread
    // load assignment for w chunk:  512 float4 ( 64 rows x 8), 2 per thread
    auto load_global = [&](int c, float4* lx, float4* lw) {
        const int k0 = c * DK;
#pragma unroll
        for (int j = 0; j < 4; j++) {
            int i = tid + 256 * j;
            int t = i >> 3, kq = i & 7;
            lx[j] = *reinterpret_cast<const float4*>(&x[(size_t)(tok_base + t) * D_DIM + k0 + kq * 4]);
        }
#pragma unroll
        for (int j = 0; j < 2; j++) {
            int i = tid + 256 * j;
            int e = i >> 3, kq = i & 7;
            lw[j] = *reinterpret_cast<const float4*>(&W[(size_t)e * D_DIM + k0 + kq * 4]);
        }
    };

    load_global(0, px, pw);

    for (int c = 0; c < NCHUNK; c++) {
        __syncthreads();  // previous compute done reading smem
        // store staged chunk to smem
#pragma unroll
        for (int j = 0; j < 4; j++) {
            int i = tid + 256 * j;
            int t = i >> 3, kq = i & 7;
            *reinterpret_cast<float4*>(&xs[t][kq * 4]) = px[j];
        }
#pragma unroll
        for (int j = 0; j < 2; j++) {
            int i = tid + 256 * j;
            int e = i >> 3, kq = i & 7;
            *reinterpret_cast<float4*>(&ws[e][kq * 4]) = pw[j];
        }
        __syncthreads();

        if (c + 1 < NCHUNK) load_global(c + 1, px, pw);  // overlap LDG with compute

        // compute: 8 tokens x 4 experts x DK
#pragma unroll
        for (int kq = 0; kq < 8; kq++) {
            float4 w0 = *reinterpret_cast<const float4*>(&ws[tx     ][kq * 4]);
            float4 w1 = *reinterpret_cast<const float4*>(&ws[tx + 16][kq * 4]);
            float4 w2 = *reinterpret_cast<const float4*>(&ws[tx + 32][kq * 4]);
            float4 w3 = *reinterpret_cast<const float4*>(&ws[tx + 48][kq * 4]);
#pragma unroll
            for (int i = 0; i < 8; i++) {
                float4 xv = *reinterpret_cast<const float4*>(&xs[ty * 8 + i][kq * 4]);
                acc[i][0] = fmaf(xv.x, w0.x, acc[i][0]);
                acc[i][0] = fmaf(xv.y, w0.y, acc[i][0]);
                acc[i][0] = fmaf(xv.z, w0.z, acc[i][0]);
                acc[i][0] = fmaf(xv.w, w0.w, acc[i][0]);
                acc[i][1] = fmaf(xv.x, w1.x, acc[i][1]);
                acc[i][1] = fmaf(xv.y, w1.y, acc[i][1]);
                acc[i][1] = fmaf(xv.z, w1.z, acc[i][1]);
                acc[i][1] = fmaf(xv.w, w1.w, acc[i][1]);
                acc[i][2] = fmaf(xv.x, w2.x, acc[i][2]);
                acc[i][2] = fmaf(xv.y, w2.y, acc[i][2]);
                acc[i][2] = fmaf(xv.z, w2.z, acc[i][2]);
                acc[i][2] = fmaf(xv.w, w2.w, acc[i][2]);
                acc[i][3] = fmaf(xv.x, w3.x, acc[i][3]);
                acc[i][3] = fmaf(xv.y, w3.y, acc[i][3]);
                acc[i][3] = fmaf(xv.z, w3.z, acc[i][3]);
                acc[i][3] = fmaf(xv.w, w3.w, acc[i][3]);
            }
        }
    }

    // ---- epilogue ----
    __syncthreads();  // done with xs/ws; reuse as probs
#pragma unroll
    for (int i = 0; i < 8; i++)
#pragma unroll
        for (int j = 0; j < 4; j++)
            probs[ty * 8 + i][tx + 16 * j] = acc[i][j];
    __syncthreads();

    const int woff = (out_size - 1) / 2;  // weights section offset (32768)

    if (tid < TOK_TILE) {
        const int t = tid;
        // top-2 on logits (ties -> lowest index, matching jax.lax.top_k)
        float v1 = -INFINITY, v2 = -INFINITY;
        int i1 = 0, i2 = 0;
#pragma unroll 8
        for (int e = 0; e < E_EXP; e++) {
            float l = probs[t][e];
            if (l > v1) { v2 = v1; i2 = i1; v1 = l; i1 = e; }
            else if (l > v2) { v2 = l; i2 = e; }
        }
        const float m = v1;
        float s = 0.0f;
#pragma unroll 8
        for (int e = 0; e < E_EXP; e++) {
            float ex = expf(probs[t][e] - m);
            probs[t][e] = ex;
            s += ex;
        }
        rZ[t] = 1.0f / s;

        // normalized top-2 weights: e1/(e1+e2), e1 = exp(v1-m) = 1
        float e2 = expf(v2 - m);
        float inv = 1.0f / (1.0f + e2);
        float w1 = inv, w2 = e2 * inv;

        int gt = tok_base + t;
        out[2 * gt    ] = (float)i1;
        out[2 * gt + 1] = (float)i2;
        out[woff + 2 * gt    ] = w1;
        out[woff + 2 * gt + 1] = w2;
    }
    __syncthreads();

    // per-block expert usage partial (deterministic order)
    if (tid < E_EXP) {
        float u = 0.0f;
        for (int t = 0; t < TOK_TILE; t++)
            u += probs[t][tid] * rZ[t];
        g_partial[blk * E_EXP + tid] = u;
    }
}

__global__ void router_aux(float* __restrict__ out, int out_size)
{
    __shared__ float red[E_EXP];
    int e = threadIdx.x;
    float u = 0.0f;
    for (int b = 0; b < NBLK; b++)
        u += g_partial[b * E_EXP + e];
    u *= (1.0f / (float)T_TOK);
    float d = u - 1.0f / (float)E_EXP;
    red[e] = d * d;
    __syncthreads();
    if (e == 0) {
        float s = 0.0f;
        for (int k = 0; k < E_EXP; k++) s += red[k];
        out[out_size - 1] = s;
    }
}

extern "C" void kernel_launch(void* const* d_in, const int* in_sizes, int n_in,
                              void* d_out, int out_size)
{
    const float* x = (const float*)d_in[0];
    const float* W = (const float*)d_in[1];
    float* out = (float*)d_out;

    router_main<<<NBLK, 256>>>(x, W, out, out_size);
    router_aux<<<1, E_EXP>>>(out, out_size);
}

// round 5
// speedup vs baseline: 2.1948x; 2.1948x over previous
#include <cuda_runtime.h>
#include <cuda_fp16.h>
#include <math.h>
#include <stdint.h>

// ---------------- problem constants ----------------
#define T_TOK    16384
#define D_DIM    2048
#define E_EXP    64
#define TOK_TILE 128
#define NBLK     (T_TOK / TOK_TILE)   // 128
#define KC       32                   // K per chunk
#define NCH      (D_DIM / KC)         // 64

// smem layout per stage: fp16 tiles, row stride 80B (64B data + 16B pad -> conflict-free ldmatrix)
#define RS    80
#define A_HI  0
#define A_LO  10240                   // 128*80
#define B_HI  20480
#define B_LO  25600                   // +64*80
#define STG   30720
#define DYN_BYTES (2 * STG)           // 61440

#define PROW 66

__device__ float g_partial[NBLK * E_EXP];

// ---------------- helpers ----------------
__device__ __forceinline__ uint32_t s2u(const void* p) {
    uint32_t a;
    asm("{ .reg .u64 t; cvta.to.shared.u64 t, %1; cvt.u32.u64 %0, t; }" : "=r"(a) : "l"(p));
    return a;
}

__device__ __forceinline__ void ldsm4(uint32_t* r, uint32_t addr) {
    asm volatile("ldmatrix.sync.aligned.m8n8.x4.shared.b16 {%0,%1,%2,%3}, [%4];"
        : "=r"(r[0]), "=r"(r[1]), "=r"(r[2]), "=r"(r[3]) : "r"(addr));
}

__device__ __forceinline__ void mma16816(float* c, const uint32_t* a, uint32_t b0, uint32_t b1) {
    asm volatile("mma.sync.aligned.m16n8k16.row.col.f32.f16.f16.f32 "
        "{%0,%1,%2,%3}, {%4,%5,%6,%7}, {%8,%9}, {%0,%1,%2,%3};"
        : "+f"(c[0]), "+f"(c[1]), "+f"(c[2]), "+f"(c[3])
        : "r"(a[0]), "r"(a[1]), "r"(a[2]), "r"(a[3]), "r"(b0), "r"(b1));
}

// split one float4 into fp16 hi/lo pairs and store (8B each) to smem
__device__ __forceinline__ void split_sts(float4 v, uint32_t ahi, uint32_t alo) {
    __half2 h0 = __floats2half2_rn(v.x, v.y);
    __half2 h1 = __floats2half2_rn(v.z, v.w);
    float2 f0 = __half22float2(h0);
    float2 f1 = __half22float2(h1);
    __half2 l0 = __floats2half2_rn(v.x - f0.x, v.y - f0.y);
    __half2 l1 = __floats2half2_rn(v.z - f1.x, v.w - f1.y);
    uint32_t u0 = *reinterpret_cast<uint32_t*>(&h0);
    uint32_t u1 = *reinterpret_cast<uint32_t*>(&h1);
    uint32_t w0 = *reinterpret_cast<uint32_t*>(&l0);
    uint32_t w1 = *reinterpret_cast<uint32_t*>(&l1);
    asm volatile("st.shared.v2.u32 [%0], {%1,%2};" :: "r"(ahi), "r"(u0), "r"(u1) : "memory");
    asm volatile("st.shared.v2.u32 [%0], {%1,%2};" :: "r"(alo), "r"(w0), "r"(w1) : "memory");
}

// ---------------- main kernel ----------------
__global__ __launch_bounds__(256, 1)
void router_hmma(const float* __restrict__ x, const float* __restrict__ W,
                 float* __restrict__ out, int out_size)
{
    extern __shared__ __align__(16) char dsm[];
    const uint32_t base = s2u(dsm);

    const int tid  = threadIdx.x;
    const int lane = tid & 31;
    const int wid  = tid >> 5;
    const int wm   = wid & 3;    // m block (32 rows)
    const int wn   = wid >> 2;   // n block (32 cols)
    const int tok_base = blockIdx.x * TOK_TILE;

    // loader assignment: A rows (tid>>3)+32j (j=0..3), B rows (tid>>3)+32j (j=0..1), q = tid&7
    const int lrow = tid >> 3;
    const int lq   = tid & 7;
    const float* gA[4];
    const float* gB[2];
#pragma unroll
    for (int j = 0; j < 4; j++)
        gA[j] = x + (size_t)(tok_base + lrow + 32 * j) * D_DIM + lq * 4;
#pragma unroll
    for (int j = 0; j < 2; j++)
        gB[j] = W + (size_t)(lrow + 32 * j) * D_DIM + lq * 4;

    // smem store addresses (per stage add STG)
    uint32_t sAd[4], sBd[2];
#pragma unroll
    for (int j = 0; j < 4; j++) sAd[j] = base + (lrow + 32 * j) * RS + lq * 8;
#pragma unroll
    for (int j = 0; j < 2; j++) sBd[j] = base + (lrow + 32 * j) * RS + lq * 8;

    float4 va[4], vb[2];

    // ldmatrix base addresses (stage 0, ks = 0); add ks*32 per kstep, STG per stage
    uint32_t a_addr[2], b_addr[2];
#pragma unroll
    for (int mi = 0; mi < 2; mi++) {
        int row = wm * 32 + mi * 16 + (lane & 15);
        int word = lane >> 4;
        a_addr[mi] = base + row * RS + word * 16;
    }
#pragma unroll
    for (int g = 0; g < 2; g++) {
        int row = wn * 32 + g * 16 + (lane & 7) + ((lane & 16) ? 8 : 0);
        int word = (lane >> 3) & 1;
        b_addr[g] = base + row * RS + word * 16;
    }

    float c[2][4][4];
#pragma unroll
    for (int mi = 0; mi < 2; mi++)
#pragma unroll
        for (int nj = 0; nj < 4; nj++)
#pragma unroll
            for (int r = 0; r < 4; r++) c[mi][nj][r] = 0.0f;

    // ---- prologue: chunk 0 load+store, chunk 1 load ----
#pragma unroll
    for (int j = 0; j < 4; j++) va[j] = *reinterpret_cast<const float4*>(gA[j]);
#pragma unroll
    for (int j = 0; j < 2; j++) vb[j] = *reinterpret_cast<const float4*>(gB[j]);
#pragma unroll
    for (int j = 0; j < 4; j++) split_sts(va[j], sAd[j] + A_HI, sAd[j] + A_LO);
#pragma unroll
    for (int j = 0; j < 2; j++) split_sts(vb[j], sBd[j] + B_HI, sBd[j] + B_LO);
#pragma unroll
    for (int j = 0; j < 4; j++) va[j] = *reinterpret_cast<const float4*>(gA[j] + KC);
#pragma unroll
    for (int j = 0; j < 2; j++) vb[j] = *reinterpret_cast<const float4*>(gB[j] + KC);
    __syncthreads();

    for (int ch = 0; ch < NCH; ch++) {
        const uint32_t sb = (ch & 1) ? STG : 0;
        // ---- compute chunk ch ----
#pragma unroll
        for (int ks = 0; ks < 2; ks++) {
            uint32_t ah[2][4], al[2][4], bh[2][4], bl[2][4];
#pragma unroll
            for (int mi = 0; mi < 2; mi++) {
                ldsm4(ah[mi], a_addr[mi] + sb + A_HI + ks * 32);
                ldsm4(al[mi], a_addr[mi] + sb + A_LO + ks * 32);
            }
#pragma unroll
            for (int g = 0; g < 2; g++) {
                ldsm4(bh[g], b_addr[g] + sb + B_HI + ks * 32);
                ldsm4(bl[g], b_addr[g] + sb + B_LO + ks * 32);
            }
#pragma unroll
            for (int mi = 0; mi < 2; mi++)
#pragma unroll
                for (int nj = 0; nj < 4; nj++) {
                    uint32_t bh0 = bh[nj >> 1][(nj & 1) * 2];
                    uint32_t bh1 = bh[nj >> 1][(nj & 1) * 2 + 1];
                    uint32_t bl0 = bl[nj >> 1][(nj & 1) * 2];
                    uint32_t bl1 = bl[nj >> 1][(nj & 1) * 2 + 1];
                    mma16816(c[mi][nj], ah[mi], bh0, bh1);  // hh
                    mma16816(c[mi][nj], ah[mi], bl0, bl1);  // hl
                    mma16816(c[mi][nj], al[mi], bh0, bh1);  // lh
                }
        }
        // ---- stage ch+1 store, chunk ch+2 load ----
        if (ch + 1 < NCH) {
            const uint32_t ss = ((ch + 1) & 1) ? STG : 0;
#pragma unroll
            for (int j = 0; j < 4; j++) split_sts(va[j], sAd[j] + ss + A_HI, sAd[j] + ss + A_LO);
#pragma unroll
            for (int j = 0; j < 2; j++) split_sts(vb[j], sBd[j] + ss + B_HI, sBd[j] + ss + B_LO);
            if (ch + 2 < NCH) {
                const int k0 = (ch + 2) * KC;
#pragma unroll
                for (int j = 0; j < 4; j++) va[j] = *reinterpret_cast<const float4*>(gA[j] + k0);
#pragma unroll
                for (int j = 0; j < 2; j++) vb[j] = *reinterpret_cast<const float4*>(gB[j] + k0);
            }
        }
        __syncthreads();
    }

    // ---------------- epilogue ----------------
    float (*probs)[PROW] = reinterpret_cast<float(*)[PROW]>(dsm);
    float* rZ = reinterpret_cast<float*>(dsm) + TOK_TILE * PROW;

    // accumulators -> smem
#pragma unroll
    for (int mi = 0; mi < 2; mi++) {
        int r0 = wm * 32 + mi * 16 + (lane >> 2);
#pragma unroll
        for (int nj = 0; nj < 4; nj++) {
            int col = wn * 32 + nj * 8 + (lane & 3) * 2;
            *reinterpret_cast<float2*>(&probs[r0][col])     = make_float2(c[mi][nj][0], c[mi][nj][1]);
            *reinterpret_cast<float2*>(&probs[r0 + 8][col]) = make_float2(c[mi][nj][2], c[mi][nj][3]);
        }
    }
    __syncthreads();

    const int woff = (out_size - 1) / 2;

    if (tid < TOK_TILE) {
        const int t = tid;
        float v1 = -INFINITY, v2 = -INFINITY;
        int i1 = 0, i2 = 0;
#pragma unroll 8
        for (int e = 0; e < E_EXP; e++) {
            float l = probs[t][e];
            if (l > v1)      { v2 = v1; i2 = i1; v1 = l; i1 = e; }
            else if (l > v2) { v2 = l;  i2 = e; }
        }
        float ssum = 0.0f;
#pragma unroll 8
        for (int e = 0; e < E_EXP; e++) {
            float p = expf(probs[t][e] - v1);
            probs[t][e] = p;
            ssum += p;
        }
        rZ[t] = 1.0f / ssum;

        float e2 = expf(v2 - v1);
        float inv = 1.0f / (1.0f + e2);
        int gt = tok_base + t;
        out[2 * gt]            = (float)i1;
        out[2 * gt + 1]        = (float)i2;
        out[woff + 2 * gt]     = inv;
        out[woff + 2 * gt + 1] = e2 * inv;
    }
    __syncthreads();

    if (tid < E_EXP) {
        float u = 0.0f;
        for (int t = 0; t < TOK_TILE; t++)
            u += probs[t][tid] * rZ[t];
        g_partial[blockIdx.x * E_EXP + tid] = u;
    }
}

// ---------------- aux loss reduction ----------------
__global__ void router_aux(float* __restrict__ out, int out_size)
{
    __shared__ float red[4][E_EXP];
    __shared__ float sq[E_EXP];
    const int tid = threadIdx.x;
    const int e = tid & 63;
    const int part = tid >> 6;            // 0..3, 32 blocks each
    float u = 0.0f;
#pragma unroll 8
    for (int b = part * 32; b < part * 32 + 32; b++)
        u += g_partial[b * E_EXP + e];
    red[part][e] = u;
    __syncthreads();
    if (tid < E_EXP) {
        float s = (red[0][tid] + red[1][tid]) + (red[2][tid] + red[3][tid]);
        s *= (1.0f / (float)T_TOK);
        float d = s - 1.0f / (float)E_EXP;
        sq[tid] = d * d;
    }
    __syncthreads();
    if (tid < 32) {
        float s = sq[tid] + sq[tid + 32];
#pragma unroll
        for (int o = 16; o > 0; o >>= 1)
            s += __shfl_down_sync(0xFFFFFFFFu, s, o);
        if (tid == 0) out[out_size - 1] = s;
    }
}

extern "C" void kernel_launch(void* const* d_in, const int* in_sizes, int n_in,
                              void* d_out, int out_size)
{
    const float* x = (const float*)d_in[0];
    const float* W = (const float*)d_in[1];
    float* out = (float*)d_out;

    cudaFuncSetAttribute(router_hmma, cudaFuncAttributeMaxDynamicSharedMemorySize, DYN_BYTES);
    router_hmma<<<NBLK, 256, DYN_BYTES>>>(x, W, out, out_size);
    router_aux<<<1, 256>>>(out, out_size);
}

// round 6
// speedup vs baseline: 2.2423x; 1.0216x over previous
#include <cuda_runtime.h>
#include <cuda_fp16.h>
#include <math.h>
#include <stdint.h>

// ---------------- problem constants ----------------
#define T_TOK    16384
#define D_DIM    2048
#define E_EXP    64
#define TOK_TILE 128
#define NBLK     (T_TOK / TOK_TILE)   // 128
#define KC       32                   // K per chunk
#define NCH      (D_DIM / KC)         // 64

// smem layout per stage: fp16 tiles, row stride 80B (64B data + 16B pad -> conflict-free ldmatrix)
#define RS    80
#define A_HI  0
#define A_LO  10240                   // 128*80
#define B_HI  20480
#define B_LO  25600                   // +64*80
#define STG   30720
#define DYN_BYTES (2 * STG)           // 61440

#define PROW 66

__device__ float g_partial[NBLK * E_EXP];
__device__ unsigned int g_cnt = 0;

// ---------------- helpers ----------------
__device__ __forceinline__ uint32_t s2u(const void* p) {
    uint32_t a;
    asm("{ .reg .u64 t; cvta.to.shared.u64 t, %1; cvt.u32.u64 %0, t; }" : "=r"(a) : "l"(p));
    return a;
}

__device__ __forceinline__ void ldsm4(uint32_t* r, uint32_t addr) {
    asm volatile("ldmatrix.sync.aligned.m8n8.x4.shared.b16 {%0,%1,%2,%3}, [%4];"
        : "=r"(r[0]), "=r"(r[1]), "=r"(r[2]), "=r"(r[3]) : "r"(addr));
}

__device__ __forceinline__ void mma16816(float* c, const uint32_t* a, uint32_t b0, uint32_t b1) {
    asm volatile("mma.sync.aligned.m16n8k16.row.col.f32.f16.f16.f32 "
        "{%0,%1,%2,%3}, {%4,%5,%6,%7}, {%8,%9}, {%0,%1,%2,%3};"
        : "+f"(c[0]), "+f"(c[1]), "+f"(c[2]), "+f"(c[3])
        : "r"(a[0]), "r"(a[1]), "r"(a[2]), "r"(a[3]), "r"(b0), "r"(b1));
}

// split one float4 into fp16 hi/lo pairs and store (8B each) to smem
__device__ __forceinline__ void split_sts(float4 v, uint32_t ahi, uint32_t alo) {
    __half2 h0 = __floats2half2_rn(v.x, v.y);
    __half2 h1 = __floats2half2_rn(v.z, v.w);
    float2 f0 = __half22float2(h0);
    float2 f1 = __half22float2(h1);
    __half2 l0 = __floats2half2_rn(v.x - f0.x, v.y - f0.y);
    __half2 l1 = __floats2half2_rn(v.z - f1.x, v.w - f1.y);
    uint32_t u0 = *reinterpret_cast<uint32_t*>(&h0);
    uint32_t u1 = *reinterpret_cast<uint32_t*>(&h1);
    uint32_t w0 = *reinterpret_cast<uint32_t*>(&l0);
    uint32_t w1 = *reinterpret_cast<uint32_t*>(&l1);
    asm volatile("st.shared.v2.u32 [%0], {%1,%2};" :: "r"(ahi), "r"(u0), "r"(u1) : "memory");
    asm volatile("st.shared.v2.u32 [%0], {%1,%2};" :: "r"(alo), "r"(w0), "r"(w1) : "memory");
}

// ---------------- main kernel ----------------
__global__ __launch_bounds__(256, 1)
void router_hmma(const float* __restrict__ x, const float* __restrict__ W,
                 float* __restrict__ out, int out_size)
{
    extern __shared__ __align__(16) char dsm[];
    const uint32_t base = s2u(dsm);

    const int tid  = threadIdx.x;
    const int lane = tid & 31;
    const int wid  = tid >> 5;
    const int wm   = wid & 3;    // m block (32 rows)
    const int wn   = wid >> 2;   // n block (32 cols)
    const int tok_base = blockIdx.x * TOK_TILE;

    // loader assignment
    const int lrow = tid >> 3;
    const int lq   = tid & 7;
    const float* gA[4];
    const float* gB[2];
#pragma unroll
    for (int j = 0; j < 4; j++)
        gA[j] = x + (size_t)(tok_base + lrow + 32 * j) * D_DIM + lq * 4;
#pragma unroll
    for (int j = 0; j < 2; j++)
        gB[j] = W + (size_t)(lrow + 32 * j) * D_DIM + lq * 4;

    uint32_t sAd[4], sBd[2];
#pragma unroll
    for (int j = 0; j < 4; j++) sAd[j] = base + (lrow + 32 * j) * RS + lq * 8;
#pragma unroll
    for (int j = 0; j < 2; j++) sBd[j] = base + (lrow + 32 * j) * RS + lq * 8;

    float4 va[4], vb[2];

    // ldmatrix base addresses (stage 0, ks=0); +ks*32, +STG per stage
    uint32_t a_addr[2], b_addr[2];
#pragma unroll
    for (int mi = 0; mi < 2; mi++) {
        int row = wm * 32 + mi * 16 + (lane & 15);
        int word = lane >> 4;
        a_addr[mi] = base + row * RS + word * 16;
    }
#pragma unroll
    for (int g = 0; g < 2; g++) {
        int row = wn * 32 + g * 16 + (lane & 7) + ((lane & 16) ? 8 : 0);
        int word = (lane >> 3) & 1;
        b_addr[g] = base + row * RS + word * 16;
    }

    float c[2][4][4];
#pragma unroll
    for (int mi = 0; mi < 2; mi++)
#pragma unroll
        for (int nj = 0; nj < 4; nj++)
#pragma unroll
            for (int r = 0; r < 4; r++) c[mi][nj][r] = 0.0f;

    // ---- prologue: chunk0 load+store, chunk1 load ----
#pragma unroll
    for (int j = 0; j < 4; j++) va[j] = *reinterpret_cast<const float4*>(gA[j]);
#pragma unroll
    for (int j = 0; j < 2; j++) vb[j] = *reinterpret_cast<const float4*>(gB[j]);
#pragma unroll
    for (int j = 0; j < 4; j++) split_sts(va[j], sAd[j] + A_HI, sAd[j] + A_LO);
#pragma unroll
    for (int j = 0; j < 2; j++) split_sts(vb[j], sBd[j] + B_HI, sBd[j] + B_LO);
#pragma unroll
    for (int j = 0; j < 4; j++) va[j] = *reinterpret_cast<const float4*>(gA[j] + KC);
#pragma unroll
    for (int j = 0; j < 2; j++) vb[j] = *reinterpret_cast<const float4*>(gB[j] + KC);
    __syncthreads();

    for (int ch = 0; ch < NCH; ch++) {
        const uint32_t sb = (ch & 1) ? STG : 0;

        // 1) issue ALL ldmatrix for this chunk first (both k-steps) — crossbar
        //    streams while independent STS/LDG issue below
        uint32_t ah[2][2][4], al[2][2][4], bh[2][2][4], bl[2][2][4];
#pragma unroll
        for (int ks = 0; ks < 2; ks++) {
#pragma unroll
            for (int mi = 0; mi < 2; mi++) {
                ldsm4(ah[ks][mi], a_addr[mi] + sb + A_HI + ks * 32);
                ldsm4(al[ks][mi], a_addr[mi] + sb + A_LO + ks * 32);
            }
#pragma unroll
            for (int g = 0; g < 2; g++) {
                ldsm4(bh[ks][g], b_addr[g] + sb + B_HI + ks * 32);
                ldsm4(bl[ks][g], b_addr[g] + sb + B_LO + ks * 32);
            }
        }

        // 2) split+store next chunk into the other buffer
        if (ch + 1 < NCH) {
            const uint32_t ss = (ch & 1) ? 0 : STG;
#pragma unroll
            for (int j = 0; j < 4; j++) split_sts(va[j], sAd[j] + ss + A_HI, sAd[j] + ss + A_LO);
#pragma unroll
            for (int j = 0; j < 2; j++) split_sts(vb[j], sBd[j] + ss + B_HI, sBd[j] + ss + B_LO);
            // 3) global loads for chunk+2
            if (ch + 2 < NCH) {
                const int k0 = (ch + 2) * KC;
#pragma unroll
                for (int j = 0; j < 4; j++) va[j] = *reinterpret_cast<const float4*>(gA[j] + k0);
#pragma unroll
                for (int j = 0; j < 2; j++) vb[j] = *reinterpret_cast<const float4*>(gB[j] + k0);
            }
        }

        // 4) HMMA consume
#pragma unroll
        for (int ks = 0; ks < 2; ks++) {
#pragma unroll
            for (int mi = 0; mi < 2; mi++)
#pragma unroll
                for (int nj = 0; nj < 4; nj++) {
                    uint32_t b0 = bh[ks][nj >> 1][(nj & 1) * 2];
                    uint32_t b1 = bh[ks][nj >> 1][(nj & 1) * 2 + 1];
                    uint32_t l0 = bl[ks][nj >> 1][(nj & 1) * 2];
                    uint32_t l1 = bl[ks][nj >> 1][(nj & 1) * 2 + 1];
                    mma16816(c[mi][nj], ah[ks][mi], b0, b1);  // hh
                    mma16816(c[mi][nj], ah[ks][mi], l0, l1);  // hl
                    mma16816(c[mi][nj], al[ks][mi], b0, b1);  // lh
                }
        }
        __syncthreads();
    }

    // ---------------- epilogue ----------------
    float (*probs)[PROW] = reinterpret_cast<float(*)[PROW]>(dsm);
    float* rZ = reinterpret_cast<float*>(dsm) + TOK_TILE * PROW;

#pragma unroll
    for (int mi = 0; mi < 2; mi++) {
        int r0 = wm * 32 + mi * 16 + (lane >> 2);
#pragma unroll
        for (int nj = 0; nj < 4; nj++) {
            int col = wn * 32 + nj * 8 + (lane & 3) * 2;
            *reinterpret_cast<float2*>(&probs[r0][col])     = make_float2(c[mi][nj][0], c[mi][nj][1]);
            *reinterpret_cast<float2*>(&probs[r0 + 8][col]) = make_float2(c[mi][nj][2], c[mi][nj][3]);
        }
    }
    __syncthreads();

    const int woff = (out_size - 1) / 2;

    if (tid < TOK_TILE) {
        const int t = tid;
        float v1 = -INFINITY, v2 = -INFINITY;
        int i1 = 0, i2 = 0;
#pragma unroll 8
        for (int e = 0; e < E_EXP; e++) {
            float l = probs[t][e];
            if (l > v1)      { v2 = v1; i2 = i1; v1 = l; i1 = e; }
            else if (l > v2) { v2 = l;  i2 = e; }
        }
        float ssum = 0.0f;
#pragma unroll 8
        for (int e = 0; e < E_EXP; e++) {
            float p = expf(probs[t][e] - v1);
            probs[t][e] = p;
            ssum += p;
        }
        rZ[t] = 1.0f / ssum;

        float e2 = expf(v2 - v1);
        float inv = 1.0f / (1.0f + e2);
        int gt = tok_base + t;
        out[2 * gt]            = (float)i1;
        out[2 * gt + 1]        = (float)i2;
        out[woff + 2 * gt]     = inv;
        out[woff + 2 * gt + 1] = e2 * inv;
    }
    __syncthreads();

    if (tid < E_EXP) {
        float u = 0.0f;
        for (int t = 0; t < TOK_TILE; t++)
            u += probs[t][tid] * rZ[t];
        g_partial[blockIdx.x * E_EXP + tid] = u;
    }

    // ---------------- fused aux-loss reduction (last block) ----------------
    __threadfence();
    __syncthreads();
    __shared__ unsigned int s_last;
    if (tid == 0) s_last = (atomicAdd(&g_cnt, 1u) == (unsigned)(NBLK - 1));
    __syncthreads();
    if (s_last) {
        __threadfence();
        float (*red)[E_EXP] = reinterpret_cast<float(*)[E_EXP]>(dsm);
        float* sq = reinterpret_cast<float*>(dsm) + 4 * E_EXP;
        const int e = tid & 63;
        const int part = tid >> 6;  // 0..3, 32 blocks each
        float u = 0.0f;
#pragma unroll 8
        for (int b = part * 32; b < part * 32 + 32; b++)
            u += g_partial[b * E_EXP + e];
        red[part][e] = u;
        __syncthreads();
        if (tid < E_EXP) {
            float s = (red[0][tid] + red[1][tid]) + (red[2][tid] + red[3][tid]);
            s *= (1.0f / (float)T_TOK);
            float d = s - 1.0f / (float)E_EXP;
            sq[tid] = d * d;
        }
        __syncthreads();
        if (tid < 32) {
            float s = sq[tid] + sq[tid + 32];
#pragma unroll
            for (int o = 16; o > 0; o >>= 1)
                s += __shfl_down_sync(0xFFFFFFFFu, s, o);
            if (tid == 0) {
                out[out_size - 1] = s;
                g_cnt = 0;  // reset for next graph replay
            }
        }
    }
}

extern "C" void kernel_launch(void* const* d_in, const int* in_sizes, int n_in,
                              void* d_out, int out_size)
{
    const float* x = (const float*)d_in[0];
    const float* W = (const float*)d_in[1];
    float* out = (float*)d_out;

    cudaFuncSetAttribute(router_hmma, cudaFuncAttributeMaxDynamicSharedMemorySize, DYN_BYTES);
    router_hmma<<<NBLK, 256, DYN_BYTES>>>(x, W, out, out_size);
}